// round 12
// baseline (speedup 1.0000x reference)
#include <cuda_runtime.h>
#include <cuda_fp16.h>
#include <cstdint>

#define ED   128
#define AD   64
#define THREADS 256
#define ROWB 272u        // padded row stride (136 fp16); frag loads conflict-free

// ---- shared memory layout (bytes) ----
#define A_OFF     0u         // 200 rows x 272 B = 54400
#define W_OFF     54400u     // 64 rows x 272 B = 17408 -> 71808 ; reused as float4 PART after GEMM
#define W2_OFF    71808u     // 64 f32 -> 72064
#define WARR_OFF  72064u     // 208 f32 -> 72896
#define CPART_OFF 72896u     // 128 f32 -> 73408
#define B2_OFF    73408u
#define SMEM_BYTES 73424u    // x3 CTAs = 220.3 KB <= 228 KB

static __device__ __forceinline__ void mma16816(
    float c[4], const uint32_t a[4], uint32_t b0, uint32_t b1)
{
    asm volatile(
        "mma.sync.aligned.m16n8k16.row.col.f32.f16.f16.f32 "
        "{%0,%1,%2,%3}, {%4,%5,%6,%7}, {%8,%9}, {%0,%1,%2,%3};"
        : "+f"(c[0]), "+f"(c[1]), "+f"(c[2]), "+f"(c[3])
        : "r"(a[0]), "r"(a[1]), "r"(a[2]), "r"(a[3]), "r"(b0), "r"(b1));
}

__global__ void __launch_bounds__(THREADS, 3)
attn_din_kernel(const float* __restrict__ behav,
                const float* __restrict__ target,
                const float* __restrict__ W1,
                const float* __restrict__ b1,
                const float* __restrict__ W2,
                const float* __restrict__ b2,
                float* __restrict__ out)
{
    extern __shared__ char smem[];
    const int tid  = threadIdx.x;
    const int wid  = tid >> 5;
    const int lane = tid & 31;
    const int b    = blockIdx.x;

    float* w2S = (float*)(smem + W2_OFF);
    float* wAr = (float*)(smem + WARR_OFF);
    float* cP  = (float*)(smem + CPART_OFF);

    if (tid < AD) w2S[tid] = W2[tid];
    if (tid == 64) *((float*)(smem + B2_OFF)) = b2[0];

    const float4* bp = (const float4*)(behav + (size_t)b * 200 * ED);

    // ================= phase 0 (warp-specialized, balanced) =================
    if (wid < 4) {
        // warps 0-3: stage A rows 0..127 (fp16), warp w -> rows w, w+4, ...
#pragma unroll 4
        for (int i = 0; i < 32; i++) {
            int r = wid + i * 4;
            float4 v = bp[r * 32 + lane];
            __half2 h01 = __floats2half2_rn(v.x, v.y);
            __half2 h23 = __floats2half2_rn(v.z, v.w);
            uint32_t off = (uint32_t)r * ROWB + (uint32_t)lane * 8u;
            *reinterpret_cast<uint2*>(smem + A_OFF + off) =
                make_uint2(*(uint32_t*)&h01, *(uint32_t*)&h23);
        }
    } else {
        // warps 4-7: build W_b[a][k] = Wx + Wd + t[k]*Wm (fp16) and c-partials.
        const int j  = tid - 128;
        const int a  = j & 63;
        const int kh = j >> 6;
        const float* tg  = target + (size_t)b * ED + kh * 64;
        const float* w1p = W1 + (size_t)(kh * 64) * AD + a;
        float cacc = (kh == 0) ? b1[a] : 0.f;
#pragma unroll 4
        for (int kk = 0; kk < 64; kk++) {
            float tk = tg[kk];                              // warp-broadcast, L2-hot
            float wx = w1p[kk * AD];                        // coalesced
            float wt = w1p[(128 * AD) + kk * AD];
            float wm = w1p[(256 * AD) + kk * AD];
            float wd = w1p[(384 * AD) + kk * AD];
            float w  = wx + wd + tk * wm;
            int k = kh * 64 + kk;
            *reinterpret_cast<__half*>(smem + W_OFF + (uint32_t)a * ROWB + (uint32_t)k * 2u)
                = __float2half_rn(w);
            cacc = fmaf(tk, wt - wd, cacc);
        }
        cP[j] = cacc;                                       // c[a] = cP[a] + cP[64+a]
    }
    __syncthreads();   // A[0..127], W, cP, w2S, b2 ready

    const int g  = lane >> 2;
    const int t2 = (lane & 3) * 2;
    const float b2v = *((const float*)(smem + B2_OFF));

    // ---- GEMM0 + epi0: tile = wid (rows 16w..16w+15), perfectly balanced ----
#pragma unroll 1
    for (int round = 0; round < 2; round++) {
        const int tile = (round == 0) ? wid : (8 + wid);
        if (tile < 13) {
            float acc[8][4];
#pragma unroll
            for (int n = 0; n < 8; n++)
#pragma unroll
                for (int i = 0; i < 4; i++) acc[n][i] = 0.f;

            // tile 12 rows 200-207 read into the W region -> finite fp16 garbage,
            // row-isolated in MMA, masked by the s<200 guard below.
#pragma unroll
            for (int ks = 0; ks < 8; ks++) {
                const uint32_t kb = (uint32_t)(ks * 16 + t2) * 2u;
                const char* base = smem + A_OFF + (uint32_t)(tile * 16 + g) * ROWB + kb;
                uint32_t a[4];
                a[0] = *(const uint32_t*)(base);
                a[1] = *(const uint32_t*)(base + 8 * ROWB);
                a[2] = *(const uint32_t*)(base + 16);
                a[3] = *(const uint32_t*)(base + 8 * ROWB + 16);
#pragma unroll
                for (int n = 0; n < 8; n++) {
                    const char* wb = smem + W_OFF + (uint32_t)(n * 8 + g) * ROWB + kb;
                    uint32_t b0  = *(const uint32_t*)(wb);
                    uint32_t b1r = *(const uint32_t*)(wb + 16);
                    mma16816(acc[n], a, b0, b1r);
                }
            }

            // epilogue: z = b2 + sum_a relu(D + c)*W2 ; wAr = sigmoid(z)
#pragma unroll
            for (int h = 0; h < 2; h++) {
                float z = 0.f;
#pragma unroll
                for (int n = 0; n < 8; n++) {
                    int col = n * 8 + t2;
                    float c0 = cP[col]     + cP[64 + col];
                    float c1 = cP[col + 1] + cP[65 + col];
                    float h0 = fmaxf(acc[n][2 * h]     + c0, 0.f);
                    float h1 = fmaxf(acc[n][2 * h + 1] + c1, 0.f);
                    z = fmaf(h0, w2S[col], z);
                    z = fmaf(h1, w2S[col + 1], z);
                }
                z += __shfl_xor_sync(0xFFFFFFFFu, z, 1);
                z += __shfl_xor_sync(0xFFFFFFFFu, z, 2);
                int s = tile * 16 + h * 8 + g;
                if ((lane & 3) == 0 && s < 208) {
                    float wgt = (s < 200) ? (1.f / (1.f + __expf(-(z + b2v)))) : 0.f;
                    wAr[s] = wgt;
                }
            }
        }

        if (round == 0) {
            // ---- stage rows 128..199 NOW, no barrier: disjoint from GEMM0 reads,
            //      early-finishing warps overlap their LDGs with laggards' MMAs ----
#pragma unroll 3
            for (int i = 0; i < 9; i++) {
                int r = 128 + wid + i * 8;
                if (r < 200) {
                    float4 v = bp[r * 32 + lane];
                    __half2 h01 = __floats2half2_rn(v.x, v.y);
                    __half2 h23 = __floats2half2_rn(v.z, v.w);
                    uint32_t off = (uint32_t)r * ROWB + (uint32_t)lane * 8u;
                    *reinterpret_cast<uint2*>(smem + A_OFF + off) =
                        make_uint2(*(uint32_t*)&h01, *(uint32_t*)&h23);
                }
            }
            __syncthreads();   // A[128..199] + wAr[0..127] ready
        }
    }
    __syncthreads();   // wAr[128..199] ready; W region now dead

    // ---- weighted sum: thread (q=wid, lane) -> 4 e-values x 25 rows ----
    {
        float4 acc4 = make_float4(0.f, 0.f, 0.f, 0.f);
        const char* base = smem + A_OFF + (uint32_t)lane * 8u;
#pragma unroll 5
        for (int i = 0; i < 25; i++) {
            int s = wid * 25 + i;
            uint2 d = *reinterpret_cast<const uint2*>(base + (uint32_t)s * ROWB);
            float2 f01 = __half22float2(*reinterpret_cast<__half2*>(&d.x));
            float2 f23 = __half22float2(*reinterpret_cast<__half2*>(&d.y));
            float ws = wAr[s];
            acc4.x = fmaf(ws, f01.x, acc4.x);
            acc4.y = fmaf(ws, f01.y, acc4.y);
            acc4.z = fmaf(ws, f23.x, acc4.z);
            acc4.w = fmaf(ws, f23.y, acc4.w);
        }
        ((float4*)(smem + W_OFF))[wid * 32 + lane] = acc4;
    }
    __syncthreads();

    if (tid < 32) {
        const float4* p = (const float4*)(smem + W_OFF);
        float4 s0 = p[tid];
#pragma unroll
        for (int k = 1; k < 8; k++) {
            float4 v = p[k * 32 + tid];
            s0.x += v.x; s0.y += v.y; s0.z += v.z; s0.w += v.w;
        }
        *reinterpret_cast<float4*>(out + (size_t)b * ED + tid * 4) = s0;
    }
}

extern "C" void kernel_launch(void* const* d_in, const int* in_sizes, int n_in,
                              void* d_out, int out_size)
{
    const float* behav  = (const float*)d_in[0];
    const float* target = (const float*)d_in[1];
    const float* W1     = (const float*)d_in[2];
    const float* b1     = (const float*)d_in[3];
    const float* W2     = (const float*)d_in[4];
    const float* b2     = (const float*)d_in[5];
    float* out = (float*)d_out;

    const int B = in_sizes[1] / ED;   // 2048

    static bool attr_set = false;
    if (!attr_set) {
        cudaFuncSetAttribute(attn_din_kernel,
                             cudaFuncAttributeMaxDynamicSharedMemorySize, (int)SMEM_BYTES);
        attr_set = true;
    }

    attn_din_kernel<<<B, THREADS, SMEM_BYTES>>>(behav, target, W1, b1, W2, b2, out);
}

// round 13
// speedup vs baseline: 1.0373x; 1.0373x over previous
#include <cuda_runtime.h>
#include <cuda_fp16.h>
#include <cstdint>

#define ED   128
#define AD   64
#define THREADS 256
#define ROWB 272u        // padded row stride (136 fp16); frag loads conflict-free

// ---- shared memory layout (bytes) ----
#define A_OFF     0u         // 128 rows x 272 B = 34816
#define W_OFF     34816u     // 64 rows x 272 B = 17408 -> 52224 ; reused as float4 PART at the end
#define W2_OFF    52224u     // 64 f32 -> 52480
#define WARR_OFF  52480u     // 128 f32 -> 52992
#define CPART_OFF 52992u     // 128 f32 -> 53504
#define B2_OFF    53504u
#define SMEM_BYTES 53520u    // (+1KB reserve) x4 CTAs = 218 KB <= 228 KB

static __device__ __forceinline__ void mma16816(
    float c[4], const uint32_t a[4], uint32_t b0, uint32_t b1)
{
    asm volatile(
        "mma.sync.aligned.m16n8k16.row.col.f32.f16.f16.f32 "
        "{%0,%1,%2,%3}, {%4,%5,%6,%7}, {%8,%9}, {%0,%1,%2,%3};"
        : "+f"(c[0]), "+f"(c[1]), "+f"(c[2]), "+f"(c[3])
        : "r"(a[0]), "r"(a[1]), "r"(a[2]), "r"(a[3]), "r"(b0), "r"(b1));
}

__global__ void __launch_bounds__(THREADS, 4)
attn_din_kernel(const float* __restrict__ behav,
                const float* __restrict__ target,
                const float* __restrict__ W1,
                const float* __restrict__ b1,
                const float* __restrict__ W2,
                const float* __restrict__ b2,
                float* __restrict__ out)
{
    extern __shared__ char smem[];
    const int tid  = threadIdx.x;
    const int wid  = tid >> 5;
    const int lane = tid & 31;
    const int b    = blockIdx.x;

    float* w2S = (float*)(smem + W2_OFF);
    float* wAr = (float*)(smem + WARR_OFF);
    float* cP  = (float*)(smem + CPART_OFF);

    if (tid < AD) w2S[tid] = W2[tid];
    if (tid == 64) *((float*)(smem + B2_OFF)) = b2[0];

    const float4* bp = (const float4*)(behav + (size_t)b * 200 * ED);

    // ================= phase 0 (warp-specialized, balanced) =================
    if (wid < 4) {
        // warps 0-3: stage A rows 0..127 (fp16), warp w -> rows w, w+4, ...
#pragma unroll 4
        for (int i = 0; i < 32; i++) {
            int r = wid + i * 4;
            float4 v = bp[r * 32 + lane];
            __half2 h01 = __floats2half2_rn(v.x, v.y);
            __half2 h23 = __floats2half2_rn(v.z, v.w);
            uint32_t off = (uint32_t)r * ROWB + (uint32_t)lane * 8u;
            *reinterpret_cast<uint2*>(smem + A_OFF + off) =
                make_uint2(*(uint32_t*)&h01, *(uint32_t*)&h23);
        }
    } else {
        // warps 4-7: build W_b[a][k] = Wx + Wd + t[k]*Wm (fp16) and c-partials.
        const int j  = tid - 128;
        const int a  = j & 63;
        const int kh = j >> 6;
        const float* tg  = target + (size_t)b * ED + kh * 64;
        const float* w1p = W1 + (size_t)(kh * 64) * AD + a;
        float cacc = (kh == 0) ? b1[a] : 0.f;
#pragma unroll 4
        for (int kk = 0; kk < 64; kk++) {
            float tk = tg[kk];                              // warp-broadcast, L2-hot
            float wx = w1p[kk * AD];                        // coalesced
            float wt = w1p[(128 * AD) + kk * AD];
            float wm = w1p[(256 * AD) + kk * AD];
            float wd = w1p[(384 * AD) + kk * AD];
            float w  = wx + wd + tk * wm;
            int k = kh * 64 + kk;
            *reinterpret_cast<__half*>(smem + W_OFF + (uint32_t)a * ROWB + (uint32_t)k * 2u)
                = __float2half_rn(w);
            cacc = fmaf(tk, wt - wd, cacc);
        }
        cP[j] = cacc;                                       // c[a] = cP[a] + cP[64+a]
    }
    __syncthreads();   // A[0..127], W, cP, w2S, b2 ready

    const int g  = lane >> 2;
    const int t2 = (lane & 3) * 2;
    const float b2v = *((const float*)(smem + B2_OFF));

    float4 acc4 = make_float4(0.f, 0.f, 0.f, 0.f);          // persistent weighted sums

    for (int half = 0; half < 2; half++) {
        const int rows_real = half ? 72 : 128;

        if (half) {
            __syncthreads();   // wsum(half0) finished reading A
            // stage A half-1 (72 rows), all warps
            const float4* bp1 = bp + 128 * 32;
            for (int r = wid; r < 72; r += 8) {
                float4 v = bp1[r * 32 + lane];
                __half2 h01 = __floats2half2_rn(v.x, v.y);
                __half2 h23 = __floats2half2_rn(v.z, v.w);
                uint32_t off = (uint32_t)r * ROWB + (uint32_t)lane * 8u;
                *reinterpret_cast<uint2*>(smem + A_OFF + off) =
                    make_uint2(*(uint32_t*)&h01, *(uint32_t*)&h23);
            }
            __syncthreads();   // A1 ready
        }

        // ---- GEMM (2 n-chunks, acc[4][4]) + epilogue: warp w -> rows [16w,16w+16) ----
        if (wid * 16 < rows_real) {
            float z0 = 0.f, z1 = 0.f;
#pragma unroll
            for (int chunk = 0; chunk < 2; chunk++) {
                float acc[4][4];
#pragma unroll
                for (int n = 0; n < 4; n++)
#pragma unroll
                    for (int i = 0; i < 4; i++) acc[n][i] = 0.f;

#pragma unroll
                for (int ks = 0; ks < 8; ks++) {
                    const uint32_t kb = (uint32_t)(ks * 16 + t2) * 2u;
                    const char* base = smem + A_OFF + (uint32_t)(wid * 16 + g) * ROWB + kb;
                    uint32_t a[4];
                    a[0] = *(const uint32_t*)(base);
                    a[1] = *(const uint32_t*)(base + 8 * ROWB);
                    a[2] = *(const uint32_t*)(base + 16);
                    a[3] = *(const uint32_t*)(base + 8 * ROWB + 16);
#pragma unroll
                    for (int n = 0; n < 4; n++) {
                        const char* wb = smem + W_OFF
                            + (uint32_t)((chunk * 4 + n) * 8 + g) * ROWB + kb;
                        uint32_t b0  = *(const uint32_t*)(wb);
                        uint32_t b1r = *(const uint32_t*)(wb + 16);
                        mma16816(acc[n], a, b0, b1r);
                    }
                }
                // partial epilogue for this chunk's 32 columns
#pragma unroll
                for (int n = 0; n < 4; n++) {
                    int col = (chunk * 4 + n) * 8 + t2;
                    float c0 = cP[col]     + cP[64 + col];
                    float c1 = cP[col + 1] + cP[65 + col];
                    z0 = fmaf(fmaxf(acc[n][0] + c0, 0.f), w2S[col],     z0);
                    z0 = fmaf(fmaxf(acc[n][1] + c1, 0.f), w2S[col + 1], z0);
                    z1 = fmaf(fmaxf(acc[n][2] + c0, 0.f), w2S[col],     z1);
                    z1 = fmaf(fmaxf(acc[n][3] + c1, 0.f), w2S[col + 1], z1);
                }
            }
            z0 += __shfl_xor_sync(0xFFFFFFFFu, z0, 1);
            z0 += __shfl_xor_sync(0xFFFFFFFFu, z0, 2);
            z1 += __shfl_xor_sync(0xFFFFFFFFu, z1, 1);
            z1 += __shfl_xor_sync(0xFFFFFFFFu, z1, 2);
            if ((lane & 3) == 0) {
                int s0 = wid * 16 + g;
                int s1 = wid * 16 + 8 + g;
                wAr[s0] = (s0 < rows_real) ? (1.f / (1.f + __expf(-(z0 + b2v)))) : 0.f;
                wAr[s1] = (s1 < rows_real) ? (1.f / (1.f + __expf(-(z1 + b2v)))) : 0.f;
            }
        }
        __syncthreads();   // wAr ready

        // ---- weighted sum: thread (q=wid, lane) -> 4 e-values x up to 16 rows ----
        {
            int lim = rows_real - wid * 16;
            if (lim > 16) lim = 16;
            const char* base = smem + A_OFF + (uint32_t)lane * 8u;
            for (int i = 0; i < lim; i++) {
                int s = wid * 16 + i;
                uint2 d = *reinterpret_cast<const uint2*>(base + (uint32_t)s * ROWB);
                float2 f01 = __half22float2(*reinterpret_cast<__half2*>(&d.x));
                float2 f23 = __half22float2(*reinterpret_cast<__half2*>(&d.y));
                float ws = wAr[s];
                acc4.x = fmaf(ws, f01.x, acc4.x);
                acc4.y = fmaf(ws, f01.y, acc4.y);
                acc4.z = fmaf(ws, f23.x, acc4.z);
                acc4.w = fmaf(ws, f23.y, acc4.w);
            }
        }
    }

    // ---- cross-group reduce (PART lives in the dead W region) and store ----
    __syncthreads();   // everyone done reading A/wAr/W
    ((float4*)(smem + W_OFF))[wid * 32 + lane] = acc4;
    __syncthreads();

    if (tid < 32) {
        const float4* p = (const float4*)(smem + W_OFF);
        float4 s0 = p[tid];
#pragma unroll
        for (int k = 1; k < 8; k++) {
            float4 v = p[k * 32 + tid];
            s0.x += v.x; s0.y += v.y; s0.z += v.z; s0.w += v.w;
        }
        *reinterpret_cast<float4*>(out + (size_t)b * ED + tid * 4) = s0;
    }
}

extern "C" void kernel_launch(void* const* d_in, const int* in_sizes, int n_in,
                              void* d_out, int out_size)
{
    const float* behav  = (const float*)d_in[0];
    const float* target = (const float*)d_in[1];
    const float* W1     = (const float*)d_in[2];
    const float* b1     = (const float*)d_in[3];
    const float* W2     = (const float*)d_in[4];
    const float* b2     = (const float*)d_in[5];
    float* out = (float*)d_out;

    const int B = in_sizes[1] / ED;   // 2048

    static bool attr_set = false;
    if (!attr_set) {
        cudaFuncSetAttribute(attn_din_kernel,
                             cudaFuncAttributeMaxDynamicSharedMemorySize, (int)SMEM_BYTES);
        attr_set = true;
    }

    attn_din_kernel<<<B, THREADS, SMEM_BYTES>>>(behav, target, W1, b1, W2, b2, out);
}

// round 14
// speedup vs baseline: 1.0847x; 1.0457x over previous
#include <cuda_runtime.h>
#include <cuda_fp16.h>
#include <cstdint>

#define ED   128
#define AD   64
#define THREADS 256
#define ROWB 272u        // padded row stride (136 fp16); frag loads conflict-free

// ---- shared memory layout (bytes) ----
#define A_OFF     0u         // 128 rows x 272 B = 34816
#define W_OFF     34816u     // 64 rows x 272 B = 17408 -> 52224 ; reused as float4 PART at the end
#define W2_OFF    52224u     // 64 f32 -> 52480
#define WARR_OFF  52480u     // 128 f32 -> 52992
#define CPART_OFF 52992u     // 128 f32 -> 53504
#define B2_OFF    53504u
#define SMEM_BYTES 53520u    // x3 CTAs = 160.6 KB (occ-3 with margin)

static __device__ __forceinline__ void mma16816(
    float c[4], const uint32_t a[4], uint32_t b0, uint32_t b1)
{
    asm volatile(
        "mma.sync.aligned.m16n8k16.row.col.f32.f16.f16.f32 "
        "{%0,%1,%2,%3}, {%4,%5,%6,%7}, {%8,%9}, {%0,%1,%2,%3};"
        : "+f"(c[0]), "+f"(c[1]), "+f"(c[2]), "+f"(c[3])
        : "r"(a[0]), "r"(a[1]), "r"(a[2]), "r"(a[3]), "r"(b0), "r"(b1));
}

__global__ void __launch_bounds__(THREADS, 3)
attn_din_kernel(const float* __restrict__ behav,
                const float* __restrict__ target,
                const float* __restrict__ W1,
                const float* __restrict__ b1,
                const float* __restrict__ W2,
                const float* __restrict__ b2,
                float* __restrict__ out)
{
    extern __shared__ char smem[];
    const int tid  = threadIdx.x;
    const int wid  = tid >> 5;
    const int lane = tid & 31;
    const int b    = blockIdx.x;

    float* w2S = (float*)(smem + W2_OFF);
    float* wAr = (float*)(smem + WARR_OFF);
    float* cP  = (float*)(smem + CPART_OFF);

    if (tid < AD) w2S[tid] = W2[tid];
    if (tid == 64) *((float*)(smem + B2_OFF)) = b2[0];

    const float4* bp = (const float4*)(behav + (size_t)b * 200 * ED);

    // ================= phase 0 (warp-specialized, balanced) =================
    if (wid < 4) {
        // warps 0-3: stage A rows 0..127 (fp16), warp w -> rows w, w+4, ... (MLP 8)
#pragma unroll 8
        for (int i = 0; i < 32; i++) {
            int r = wid + i * 4;
            float4 v = bp[r * 32 + lane];
            __half2 h01 = __floats2half2_rn(v.x, v.y);
            __half2 h23 = __floats2half2_rn(v.z, v.w);
            uint32_t off = (uint32_t)r * ROWB + (uint32_t)lane * 8u;
            *reinterpret_cast<uint2*>(smem + A_OFF + off) =
                make_uint2(*(uint32_t*)&h01, *(uint32_t*)&h23);
        }
    } else {
        // warps 4-7: build W_b[a][k] = Wx + Wd + t[k]*Wm (fp16) and c-partials.
        const int j  = tid - 128;
        const int a  = j & 63;
        const int kh = j >> 6;
        const float* tg  = target + (size_t)b * ED + kh * 64;
        const float* w1p = W1 + (size_t)(kh * 64) * AD + a;
        float cacc = (kh == 0) ? b1[a] : 0.f;
#pragma unroll 4
        for (int kk = 0; kk < 64; kk++) {
            float tk = tg[kk];                              // warp-broadcast, L2-hot
            float wx = w1p[kk * AD];                        // coalesced
            float wt = w1p[(128 * AD) + kk * AD];
            float wm = w1p[(256 * AD) + kk * AD];
            float wd = w1p[(384 * AD) + kk * AD];
            float w  = wx + wd + tk * wm;
            int k = kh * 64 + kk;
            *reinterpret_cast<__half*>(smem + W_OFF + (uint32_t)a * ROWB + (uint32_t)k * 2u)
                = __float2half_rn(w);
            cacc = fmaf(tk, wt - wd, cacc);
        }
        cP[j] = cacc;                                       // c[a] = cP[a] + cP[64+a]
    }
    __syncthreads();   // A[0..127], W, cP, w2S, b2 ready

    const int g  = lane >> 2;
    const int t2 = (lane & 3) * 2;
    const float b2v = *((const float*)(smem + B2_OFF));

    float4 acc4 = make_float4(0.f, 0.f, 0.f, 0.f);          // persistent weighted sums

    for (int half = 0; half < 2; half++) {
        const int rows_real = half ? 72 : 128;

        if (half) {
            __syncthreads();   // wsum(half0) finished reading A
            // stage A half-1 (72 rows), all warps
            const float4* bp1 = bp + 128 * 32;
#pragma unroll 3
            for (int r = wid; r < 72; r += 8) {
                float4 v = bp1[r * 32 + lane];
                __half2 h01 = __floats2half2_rn(v.x, v.y);
                __half2 h23 = __floats2half2_rn(v.z, v.w);
                uint32_t off = (uint32_t)r * ROWB + (uint32_t)lane * 8u;
                *reinterpret_cast<uint2*>(smem + A_OFF + off) =
                    make_uint2(*(uint32_t*)&h01, *(uint32_t*)&h23);
            }
            __syncthreads();   // A1 ready
        }

        // ---- GEMM: warp w -> rows [16w,16w+16) x [64], scalar frag loads ----
        float acc[8][4];
#pragma unroll
        for (int n = 0; n < 8; n++)
#pragma unroll
            for (int i = 0; i < 4; i++) acc[n][i] = 0.f;

        if (wid * 16 < rows_real) {
#pragma unroll
            for (int ks = 0; ks < 8; ks++) {
                const uint32_t kb = (uint32_t)(ks * 16 + t2) * 2u;
                const char* base = smem + A_OFF + (uint32_t)(wid * 16 + g) * ROWB + kb;
                uint32_t a[4];
                a[0] = *(const uint32_t*)(base);
                a[1] = *(const uint32_t*)(base + 8 * ROWB);
                a[2] = *(const uint32_t*)(base + 16);
                a[3] = *(const uint32_t*)(base + 8 * ROWB + 16);
#pragma unroll
                for (int n = 0; n < 8; n++) {
                    const char* wb = smem + W_OFF + (uint32_t)(n * 8 + g) * ROWB + kb;
                    uint32_t b0  = *(const uint32_t*)(wb);
                    uint32_t b1r = *(const uint32_t*)(wb + 16);
                    mma16816(acc[n], a, b0, b1r);
                }
            }

            // ---- epilogue (c hoisted per n): z[h] = sum relu(D+c)*W2 ----
            float z[2] = {0.f, 0.f};
#pragma unroll
            for (int n = 0; n < 8; n++) {
                int col = n * 8 + t2;
                float c0 = cP[col]     + cP[64 + col];
                float c1 = cP[col + 1] + cP[65 + col];
#pragma unroll
                for (int h = 0; h < 2; h++) {
                    float h0 = fmaxf(acc[n][2 * h]     + c0, 0.f);
                    float h1 = fmaxf(acc[n][2 * h + 1] + c1, 0.f);
                    z[h] = fmaf(h0, w2S[col], z[h]);
                    z[h] = fmaf(h1, w2S[col + 1], z[h]);
                }
            }
#pragma unroll
            for (int h = 0; h < 2; h++) {
                float zz = z[h];
                zz += __shfl_xor_sync(0xFFFFFFFFu, zz, 1);
                zz += __shfl_xor_sync(0xFFFFFFFFu, zz, 2);
                int s = wid * 16 + h * 8 + g;
                if ((lane & 3) == 0) {
                    float wgt = (s < rows_real) ? (1.f / (1.f + __expf(-(zz + b2v)))) : 0.f;
                    wAr[s] = wgt;
                }
            }
        }
        __syncthreads();   // wAr ready

        // ---- weighted sum: thread (q=wid, lane) -> 4 e-values x up to 16 rows ----
        {
            int lim = rows_real - wid * 16;
            if (lim > 16) lim = 16;
            const char* base = smem + A_OFF + (uint32_t)lane * 8u;
            for (int i = 0; i < lim; i++) {
                int s = wid * 16 + i;
                uint2 d = *reinterpret_cast<const uint2*>(base + (uint32_t)s * ROWB);
                float2 f01 = __half22float2(*reinterpret_cast<__half2*>(&d.x));
                float2 f23 = __half22float2(*reinterpret_cast<__half2*>(&d.y));
                float ws = wAr[s];
                acc4.x = fmaf(ws, f01.x, acc4.x);
                acc4.y = fmaf(ws, f01.y, acc4.y);
                acc4.z = fmaf(ws, f23.x, acc4.z);
                acc4.w = fmaf(ws, f23.y, acc4.w);
            }
        }
    }

    // ---- cross-group reduce (PART in dead W region; write needs no extra sync:
    //      W's last reader was GEMM1 which precedes the wAr barrier) ----
    ((float4*)(smem + W_OFF))[wid * 32 + lane] = acc4;
    __syncthreads();

    if (tid < 32) {
        const float4* p = (const float4*)(smem + W_OFF);
        float4 s0 = p[tid];
#pragma unroll
        for (int k = 1; k < 8; k++) {
            float4 v = p[k * 32 + tid];
            s0.x += v.x; s0.y += v.y; s0.z += v.z; s0.w += v.w;
        }
        *reinterpret_cast<float4*>(out + (size_t)b * ED + tid * 4) = s0;
    }
}

extern "C" void kernel_launch(void* const* d_in, const int* in_sizes, int n_in,
                              void* d_out, int out_size)
{
    const float* behav  = (const float*)d_in[0];
    const float* target = (const float*)d_in[1];
    const float* W1     = (const float*)d_in[2];
    const float* b1     = (const float*)d_in[3];
    const float* W2     = (const float*)d_in[4];
    const float* b2     = (const float*)d_in[5];
    float* out = (float*)d_out;

    const int B = in_sizes[1] / ED;   // 2048

    static bool attr_set = false;
    if (!attr_set) {
        cudaFuncSetAttribute(attn_din_kernel,
                             cudaFuncAttributeMaxDynamicSharedMemorySize, (int)SMEM_BYTES);
        attr_set = true;
    }

    attn_din_kernel<<<B, THREADS, SMEM_BYTES>>>(behav, target, W1, b1, W2, b2, out);
}

// round 15
// speedup vs baseline: 1.1355x; 1.0469x over previous
#include <cuda_runtime.h>
#include <cuda_fp16.h>
#include <cstdint>

#define ED   128
#define AD   64
#define THREADS 256
#define ROWB 272u        // padded row stride (136 fp16); frag loads conflict-free

// ---- shared memory layout (bytes) ----
#define A_OFF     0u         // 128 rows x 272 B = 34816
#define W_OFF     34816u     // 64 rows x 272 B = 17408 -> 52224 ; reused as float4 PART at the end
#define W2_OFF    52224u     // 64 f32 -> 52480
#define WARR_OFF  52480u     // 128 f32 -> 52992
#define CPART_OFF 52992u     // 128 f32 -> 53504
#define B2_OFF    53504u
#define SMEM_BYTES 53520u    // x3 CTAs = 160.6 KB (occ-3 with margin)

static __device__ __forceinline__ void mma16816(
    float c[4], const uint32_t a[4], uint32_t b0, uint32_t b1)
{
    asm volatile(
        "mma.sync.aligned.m16n8k16.row.col.f32.f16.f16.f32 "
        "{%0,%1,%2,%3}, {%4,%5,%6,%7}, {%8,%9}, {%0,%1,%2,%3};"
        : "+f"(c[0]), "+f"(c[1]), "+f"(c[2]), "+f"(c[3])
        : "r"(a[0]), "r"(a[1]), "r"(a[2]), "r"(a[3]), "r"(b0), "r"(b1));
}

__global__ void __launch_bounds__(THREADS, 3)
attn_din_kernel(const float* __restrict__ behav,
                const float* __restrict__ target,
                const float* __restrict__ W1,
                const float* __restrict__ b1,
                const float* __restrict__ W2,
                const float* __restrict__ b2,
                float* __restrict__ out)
{
    extern __shared__ char smem[];
    const int tid  = threadIdx.x;
    const int wid  = tid >> 5;
    const int lane = tid & 31;
    const int b    = blockIdx.x;

    float* w2S = (float*)(smem + W2_OFF);
    float* wAr = (float*)(smem + WARR_OFF);
    float* cP  = (float*)(smem + CPART_OFF);

    if (tid < AD) w2S[tid] = W2[tid];
    if (tid == 64) *((float*)(smem + B2_OFF)) = b2[0];

    const float4* bp = (const float4*)(behav + (size_t)b * 200 * ED);

    // ================= phase 0 (warp-specialized, balanced) =================
    if (wid < 4) {
        // warps 0-3: stage A rows 0..127 (fp16), warp w -> rows w, w+4, ... (MLP 8)
#pragma unroll 8
        for (int i = 0; i < 32; i++) {
            int r = wid + i * 4;
            float4 v = bp[r * 32 + lane];
            __half2 h01 = __floats2half2_rn(v.x, v.y);
            __half2 h23 = __floats2half2_rn(v.z, v.w);
            uint32_t off = (uint32_t)r * ROWB + (uint32_t)lane * 8u;
            *reinterpret_cast<uint2*>(smem + A_OFF + off) =
                make_uint2(*(uint32_t*)&h01, *(uint32_t*)&h23);
        }
    } else {
        // warps 4-7: build W_b[a][k] = Wx + Wd + t[k]*Wm (fp16) and c-partials.
        const int j  = tid - 128;
        const int a  = j & 63;
        const int kh = j >> 6;
        const float* tg  = target + (size_t)b * ED + kh * 64;
        const float* w1p = W1 + (size_t)(kh * 64) * AD + a;
        float cacc = (kh == 0) ? b1[a] : 0.f;
#pragma unroll 4
        for (int kk = 0; kk < 64; kk++) {
            float tk = tg[kk];                              // warp-broadcast, L2-hot
            float wx = w1p[kk * AD];                        // coalesced
            float wt = w1p[(128 * AD) + kk * AD];
            float wm = w1p[(256 * AD) + kk * AD];
            float wd = w1p[(384 * AD) + kk * AD];
            float w  = wx + wd + tk * wm;
            int k = kh * 64 + kk;
            *reinterpret_cast<__half*>(smem + W_OFF + (uint32_t)a * ROWB + (uint32_t)k * 2u)
                = __float2half_rn(w);
            cacc = fmaf(tk, wt - wd, cacc);
        }
        cP[j] = cacc;                                       // c[a] = cP[a] + cP[64+a]
    }
    __syncthreads();   // A[0..127], W, cP, w2S, b2 ready

    const int g  = lane >> 2;
    const int t2 = (lane & 3) * 2;
    const float b2v = *((const float*)(smem + B2_OFF));

    float4 acc4 = make_float4(0.f, 0.f, 0.f, 0.f);          // persistent weighted sums

    // ======================= half 0: GEMM + epilogue ========================
    {
        float acc[8][4];
#pragma unroll
        for (int n = 0; n < 8; n++)
#pragma unroll
            for (int i = 0; i < 4; i++) acc[n][i] = 0.f;

#pragma unroll
        for (int ks = 0; ks < 8; ks++) {
            const uint32_t kb = (uint32_t)(ks * 16 + t2) * 2u;
            const char* base = smem + A_OFF + (uint32_t)(wid * 16 + g) * ROWB + kb;
            uint32_t a[4];
            a[0] = *(const uint32_t*)(base);
            a[1] = *(const uint32_t*)(base + 8 * ROWB);
            a[2] = *(const uint32_t*)(base + 16);
            a[3] = *(const uint32_t*)(base + 8 * ROWB + 16);
#pragma unroll
            for (int n = 0; n < 8; n++) {
                const char* wb = smem + W_OFF + (uint32_t)(n * 8 + g) * ROWB + kb;
                uint32_t b0  = *(const uint32_t*)(wb);
                uint32_t b1r = *(const uint32_t*)(wb + 16);
                mma16816(acc[n], a, b0, b1r);
            }
        }

        float z[2] = {0.f, 0.f};
#pragma unroll
        for (int n = 0; n < 8; n++) {
            int col = n * 8 + t2;
            float c0 = cP[col]     + cP[64 + col];
            float c1 = cP[col + 1] + cP[65 + col];
#pragma unroll
            for (int h = 0; h < 2; h++) {
                float h0 = fmaxf(acc[n][2 * h]     + c0, 0.f);
                float h1 = fmaxf(acc[n][2 * h + 1] + c1, 0.f);
                z[h] = fmaf(h0, w2S[col], z[h]);
                z[h] = fmaf(h1, w2S[col + 1], z[h]);
            }
        }
#pragma unroll
        for (int h = 0; h < 2; h++) {
            float zz = z[h];
            zz += __shfl_xor_sync(0xFFFFFFFFu, zz, 1);
            zz += __shfl_xor_sync(0xFFFFFFFFu, zz, 2);
            if ((lane & 3) == 0)
                wAr[wid * 16 + h * 8 + g] = 1.f / (1.f + __expf(-(zz + b2v)));
        }
    }
    __syncthreads();   // wAr[0..127] ready

    // ===== prefetch half-1 rows into REGISTERS (loads overlap wsum-0) =====
    float4 v9[9];
#pragma unroll
    for (int i = 0; i < 9; i++)
        v9[i] = bp[(128 + wid * 9 + i) * 32 + lane];

    // ---- weighted sum half 0: thread (wid, lane) -> 4 e-values x 16 rows ----
    {
        const char* base = smem + A_OFF + (uint32_t)lane * 8u;
#pragma unroll 4
        for (int i = 0; i < 16; i++) {
            int s = wid * 16 + i;
            uint2 d = *reinterpret_cast<const uint2*>(base + (uint32_t)s * ROWB);
            float2 f01 = __half22float2(*reinterpret_cast<__half2*>(&d.x));
            float2 f23 = __half22float2(*reinterpret_cast<__half2*>(&d.y));
            float ws = wAr[s];
            acc4.x = fmaf(ws, f01.x, acc4.x);
            acc4.y = fmaf(ws, f01.y, acc4.y);
            acc4.z = fmaf(ws, f23.x, acc4.z);
            acc4.w = fmaf(ws, f23.y, acc4.w);
        }
    }
    __syncthreads();   // wsum-0 done reading A; v9 loads have had wsum-0 to land

    // ---- store half-1 (72 rows) from registers to A smem ----
#pragma unroll
    for (int i = 0; i < 9; i++) {
        int r = wid * 9 + i;           // local row 0..71
        __half2 h01 = __floats2half2_rn(v9[i].x, v9[i].y);
        __half2 h23 = __floats2half2_rn(v9[i].z, v9[i].w);
        uint32_t off = (uint32_t)r * ROWB + (uint32_t)lane * 8u;
        *reinterpret_cast<uint2*>(smem + A_OFF + off) =
            make_uint2(*(uint32_t*)&h01, *(uint32_t*)&h23);
    }
    __syncthreads();   // A[0..71] = rows 128..199 ready

    // ======================= half 1: GEMM + epilogue ========================
    if (wid * 16 < 72) {               // warps 0-4
        float acc[8][4];
#pragma unroll
        for (int n = 0; n < 8; n++)
#pragma unroll
            for (int i = 0; i < 4; i++) acc[n][i] = 0.f;

#pragma unroll
        for (int ks = 0; ks < 8; ks++) {
            const uint32_t kb = (uint32_t)(ks * 16 + t2) * 2u;
            const char* base = smem + A_OFF + (uint32_t)(wid * 16 + g) * ROWB + kb;
            uint32_t a[4];
            a[0] = *(const uint32_t*)(base);
            a[1] = *(const uint32_t*)(base + 8 * ROWB);
            a[2] = *(const uint32_t*)(base + 16);
            a[3] = *(const uint32_t*)(base + 8 * ROWB + 16);
#pragma unroll
            for (int n = 0; n < 8; n++) {
                const char* wb = smem + W_OFF + (uint32_t)(n * 8 + g) * ROWB + kb;
                uint32_t b0  = *(const uint32_t*)(wb);
                uint32_t b1r = *(const uint32_t*)(wb + 16);
                mma16816(acc[n], a, b0, b1r);
            }
        }

        float z[2] = {0.f, 0.f};
#pragma unroll
        for (int n = 0; n < 8; n++) {
            int col = n * 8 + t2;
            float c0 = cP[col]     + cP[64 + col];
            float c1 = cP[col + 1] + cP[65 + col];
#pragma unroll
            for (int h = 0; h < 2; h++) {
                float h0 = fmaxf(acc[n][2 * h]     + c0, 0.f);
                float h1 = fmaxf(acc[n][2 * h + 1] + c1, 0.f);
                z[h] = fmaf(h0, w2S[col], z[h]);
                z[h] = fmaf(h1, w2S[col + 1], z[h]);
            }
        }
#pragma unroll
        for (int h = 0; h < 2; h++) {
            float zz = z[h];
            zz += __shfl_xor_sync(0xFFFFFFFFu, zz, 1);
            zz += __shfl_xor_sync(0xFFFFFFFFu, zz, 2);
            int s = wid * 16 + h * 8 + g;
            if ((lane & 3) == 0)
                wAr[s] = (s < 72) ? (1.f / (1.f + __expf(-(zz + b2v)))) : 0.f;
        }
    }
    __syncthreads();   // wAr[0..71] (half-1) ready

    // ---- weighted sum half 1 ----
    {
        int lim = 72 - wid * 16;
        if (lim > 16) lim = 16;
        const char* base = smem + A_OFF + (uint32_t)lane * 8u;
        for (int i = 0; i < lim; i++) {
            int s = wid * 16 + i;
            uint2 d = *reinterpret_cast<const uint2*>(base + (uint32_t)s * ROWB);
            float2 f01 = __half22float2(*reinterpret_cast<__half2*>(&d.x));
            float2 f23 = __half22float2(*reinterpret_cast<__half2*>(&d.y));
            float ws = wAr[s];
            acc4.x = fmaf(ws, f01.x, acc4.x);
            acc4.y = fmaf(ws, f01.y, acc4.y);
            acc4.z = fmaf(ws, f23.x, acc4.z);
            acc4.w = fmaf(ws, f23.y, acc4.w);
        }
    }

    // ---- cross-group reduce (PART in dead W region) and store ----
    __syncthreads();   // everyone done with A/wAr/W
    ((float4*)(smem + W_OFF))[wid * 32 + lane] = acc4;
    __syncthreads();

    if (tid < 32) {
        const float4* p = (const float4*)(smem + W_OFF);
        float4 s0 = p[tid];
#pragma unroll
        for (int k = 1; k < 8; k++) {
            float4 vv = p[k * 32 + tid];
            s0.x += vv.x; s0.y += vv.y; s0.z += vv.z; s0.w += vv.w;
        }
        *reinterpret_cast<float4*>(out + (size_t)b * ED + tid * 4) = s0;
    }
}

extern "C" void kernel_launch(void* const* d_in, const int* in_sizes, int n_in,
                              void* d_out, int out_size)
{
    const float* behav  = (const float*)d_in[0];
    const float* target = (const float*)d_in[1];
    const float* W1     = (const float*)d_in[2];
    const float* b1     = (const float*)d_in[3];
    const float* W2     = (const float*)d_in[4];
    const float* b2     = (const float*)d_in[5];
    float* out = (float*)d_out;

    const int B = in_sizes[1] / ED;   // 2048

    static bool attr_set = false;
    if (!attr_set) {
        cudaFuncSetAttribute(attn_din_kernel,
                             cudaFuncAttributeMaxDynamicSharedMemorySize, (int)SMEM_BYTES);
        attr_set = true;
    }

    attn_din_kernel<<<B, THREADS, SMEM_BYTES>>>(behav, target, W1, b1, W2, b2, out);
}

// round 16
// speedup vs baseline: 1.1856x; 1.0441x over previous
#include <cuda_runtime.h>
#include <cuda_fp16.h>
#include <cstdint>

#define ED   128
#define AD   64
#define THREADS 256
#define ROWB 272u        // padded row stride (136 fp16); frag loads conflict-free

// ---- shared memory layout (bytes) ----
#define A_OFF     0u         // 128 rows x 272 B = 34816
#define W_OFF     34816u     // 64 rows x 272 B = 17408 -> 52224 ; reused as float4 PART at the end
#define W2_OFF    52224u     // 64 f32 -> 52480
#define WARR_OFF  52480u     // 128 f32 -> 52992
#define CPART_OFF 52992u     // 128 f32 -> 53504
#define B2_OFF    53504u
#define SMEM_BYTES 53520u    // x3 CTAs = 160.6 KB (occ-3 with margin)

static __device__ __forceinline__ void mma16816(
    float c[4], const uint32_t a[4], uint32_t b0, uint32_t b1)
{
    asm volatile(
        "mma.sync.aligned.m16n8k16.row.col.f32.f16.f16.f32 "
        "{%0,%1,%2,%3}, {%4,%5,%6,%7}, {%8,%9}, {%0,%1,%2,%3};"
        : "+f"(c[0]), "+f"(c[1]), "+f"(c[2]), "+f"(c[3])
        : "r"(a[0]), "r"(a[1]), "r"(a[2]), "r"(a[3]), "r"(b0), "r"(b1));
}

__global__ void __launch_bounds__(THREADS, 3)
attn_din_kernel(const float* __restrict__ behav,
                const float* __restrict__ target,
                const float* __restrict__ W1,
                const float* __restrict__ b1,
                const float* __restrict__ W2,
                const float* __restrict__ b2,
                float* __restrict__ out)
{
    extern __shared__ char smem[];
    const int tid  = threadIdx.x;
    const int wid  = tid >> 5;
    const int lane = tid & 31;
    const int b    = blockIdx.x;

    float* w2S = (float*)(smem + W2_OFF);
    float* wAr = (float*)(smem + WARR_OFF);
    float* cP  = (float*)(smem + CPART_OFF);

    if (tid < AD) w2S[tid] = W2[tid];
    if (tid == 64) *((float*)(smem + B2_OFF)) = b2[0];

    const float4* bp = (const float4*)(behav + (size_t)b * 200 * ED);

    // ================= phase 0 (warp-specialized, balanced) =================
    if (wid < 4) {
        // warps 0-3: stage A rows 0..127 (fp16), warp w -> rows w, w+4, ... (MLP 8)
#pragma unroll 8
        for (int i = 0; i < 32; i++) {
            int r = wid + i * 4;
            float4 v = bp[r * 32 + lane];
            __half2 h01 = __floats2half2_rn(v.x, v.y);
            __half2 h23 = __floats2half2_rn(v.z, v.w);
            uint32_t off = (uint32_t)r * ROWB + (uint32_t)lane * 8u;
            *reinterpret_cast<uint2*>(smem + A_OFF + off) =
                make_uint2(*(uint32_t*)&h01, *(uint32_t*)&h23);
        }
    } else {
        // warps 4-7: build W_b[a][k] = Wx + Wd + t[k]*Wm (fp16) and c-partials.
        const int j  = tid - 128;
        const int a  = j & 63;
        const int kh = j >> 6;
        const float* tg  = target + (size_t)b * ED + kh * 64;
        const float* w1p = W1 + (size_t)(kh * 64) * AD + a;
        float cacc = (kh == 0) ? b1[a] : 0.f;
#pragma unroll 4
        for (int kk = 0; kk < 64; kk++) {
            float tk = tg[kk];                              // warp-broadcast, L2-hot
            float wx = w1p[kk * AD];                        // coalesced
            float wt = w1p[(128 * AD) + kk * AD];
            float wm = w1p[(256 * AD) + kk * AD];
            float wd = w1p[(384 * AD) + kk * AD];
            float w  = wx + wd + tk * wm;
            int k = kh * 64 + kk;
            *reinterpret_cast<__half*>(smem + W_OFF + (uint32_t)a * ROWB + (uint32_t)k * 2u)
                = __float2half_rn(w);
            cacc = fmaf(tk, wt - wd, cacc);
        }
        cP[j] = cacc;                                       // c[a] = cP[a] + cP[64+a]
    }
    __syncthreads();   // A[0..127], W, cP, w2S, b2 ready

    const int g  = lane >> 2;
    const int t2 = (lane & 3) * 2;
    const float b2v = *((const float*)(smem + B2_OFF));

    float4 acc4 = make_float4(0.f, 0.f, 0.f, 0.f);          // persistent weighted sums

    // ======================= half 0: GEMM + epilogue ========================
    {
        float acc[8][4];
#pragma unroll
        for (int n = 0; n < 8; n++)
#pragma unroll
            for (int i = 0; i < 4; i++) acc[n][i] = 0.f;

#pragma unroll
        for (int ks = 0; ks < 8; ks++) {
            const uint32_t kb = (uint32_t)(ks * 16 + t2) * 2u;
            const char* base = smem + A_OFF + (uint32_t)(wid * 16 + g) * ROWB + kb;
            uint32_t a[4];
            a[0] = *(const uint32_t*)(base);
            a[1] = *(const uint32_t*)(base + 8 * ROWB);
            a[2] = *(const uint32_t*)(base + 16);
            a[3] = *(const uint32_t*)(base + 8 * ROWB + 16);
#pragma unroll
            for (int n = 0; n < 8; n++) {
                const char* wb = smem + W_OFF + (uint32_t)(n * 8 + g) * ROWB + kb;
                uint32_t b0  = *(const uint32_t*)(wb);
                uint32_t b1r = *(const uint32_t*)(wb + 16);
                mma16816(acc[n], a, b0, b1r);
            }
        }

        float z[2] = {0.f, 0.f};
#pragma unroll
        for (int n = 0; n < 8; n++) {
            int col = n * 8 + t2;
            float c0 = cP[col]     + cP[64 + col];
            float c1 = cP[col + 1] + cP[65 + col];
#pragma unroll
            for (int h = 0; h < 2; h++) {
                float h0 = fmaxf(acc[n][2 * h]     + c0, 0.f);
                float h1 = fmaxf(acc[n][2 * h + 1] + c1, 0.f);
                z[h] = fmaf(h0, w2S[col], z[h]);
                z[h] = fmaf(h1, w2S[col + 1], z[h]);
            }
        }
#pragma unroll
        for (int h = 0; h < 2; h++) {
            float zz = z[h];
            zz += __shfl_xor_sync(0xFFFFFFFFu, zz, 1);
            zz += __shfl_xor_sync(0xFFFFFFFFu, zz, 2);
            if ((lane & 3) == 0)
                wAr[wid * 16 + h * 8 + g] = 1.f / (1.f + __expf(-(zz + b2v)));
        }
    }
    __syncthreads();   // wAr[0..127] ready

    // ===== prefetch half-1 rows into REGISTERS (loads overlap wsum-0) =====
    float4 v9[9];
#pragma unroll
    for (int i = 0; i < 9; i++)
        v9[i] = bp[(128 + wid * 9 + i) * 32 + lane];

    // ---- weighted sum half 0: thread (wid, lane) -> 4 e-values x 16 rows ----
    {
        const char* base = smem + A_OFF + (uint32_t)lane * 8u;
#pragma unroll 4
        for (int i = 0; i < 16; i++) {
            int s = wid * 16 + i;
            uint2 d = *reinterpret_cast<const uint2*>(base + (uint32_t)s * ROWB);
            float2 f01 = __half22float2(*reinterpret_cast<__half2*>(&d.x));
            float2 f23 = __half22float2(*reinterpret_cast<__half2*>(&d.y));
            float ws = wAr[s];
            acc4.x = fmaf(ws, f01.x, acc4.x);
            acc4.y = fmaf(ws, f01.y, acc4.y);
            acc4.z = fmaf(ws, f23.x, acc4.z);
            acc4.w = fmaf(ws, f23.y, acc4.w);
        }
    }
    __syncthreads();   // wsum-0 done reading A; v9 loads have had wsum-0 to land

    // ---- convert + store half-1 (72 rows); KEEP fp16 copies in registers ----
    uint2 h9[9];
#pragma unroll
    for (int i = 0; i < 9; i++) {
        int r = wid * 9 + i;           // local row 0..71
        __half2 h01 = __floats2half2_rn(v9[i].x, v9[i].y);
        __half2 h23 = __floats2half2_rn(v9[i].z, v9[i].w);
        h9[i] = make_uint2(*(uint32_t*)&h01, *(uint32_t*)&h23);
        uint32_t off = (uint32_t)r * ROWB + (uint32_t)lane * 8u;
        *reinterpret_cast<uint2*>(smem + A_OFF + off) = h9[i];
    }
    __syncthreads();   // A[0..71] = rows 128..199 ready

    // ======================= half 1: GEMM + epilogue ========================
    if (wid * 16 < 72) {               // warps 0-4
        float acc[8][4];
#pragma unroll
        for (int n = 0; n < 8; n++)
#pragma unroll
            for (int i = 0; i < 4; i++) acc[n][i] = 0.f;

#pragma unroll
        for (int ks = 0; ks < 8; ks++) {
            const uint32_t kb = (uint32_t)(ks * 16 + t2) * 2u;
            const char* base = smem + A_OFF + (uint32_t)(wid * 16 + g) * ROWB + kb;
            uint32_t a[4];
            a[0] = *(const uint32_t*)(base);
            a[1] = *(const uint32_t*)(base + 8 * ROWB);
            a[2] = *(const uint32_t*)(base + 16);
            a[3] = *(const uint32_t*)(base + 8 * ROWB + 16);
#pragma unroll
            for (int n = 0; n < 8; n++) {
                const char* wb = smem + W_OFF + (uint32_t)(n * 8 + g) * ROWB + kb;
                uint32_t b0  = *(const uint32_t*)(wb);
                uint32_t b1r = *(const uint32_t*)(wb + 16);
                mma16816(acc[n], a, b0, b1r);
            }
        }

        float z[2] = {0.f, 0.f};
#pragma unroll
        for (int n = 0; n < 8; n++) {
            int col = n * 8 + t2;
            float c0 = cP[col]     + cP[64 + col];
            float c1 = cP[col + 1] + cP[65 + col];
#pragma unroll
            for (int h = 0; h < 2; h++) {
                float h0 = fmaxf(acc[n][2 * h]     + c0, 0.f);
                float h1 = fmaxf(acc[n][2 * h + 1] + c1, 0.f);
                z[h] = fmaf(h0, w2S[col], z[h]);
                z[h] = fmaf(h1, w2S[col + 1], z[h]);
            }
        }
#pragma unroll
        for (int h = 0; h < 2; h++) {
            float zz = z[h];
            zz += __shfl_xor_sync(0xFFFFFFFFu, zz, 1);
            zz += __shfl_xor_sync(0xFFFFFFFFu, zz, 2);
            int s = wid * 16 + h * 8 + g;
            if ((lane & 3) == 0)
                wAr[s] = (s < 72) ? (1.f / (1.f + __expf(-(zz + b2v)))) : 0.f;
        }
    }
    __syncthreads();   // wAr[0..71] (half-1) ready

    // ---- weighted sum half 1: ENTIRELY from registers (h9) ----
#pragma unroll
    for (int i = 0; i < 9; i++) {
        float ws = wAr[wid * 9 + i];   // lane-uniform broadcast
        float2 f01 = __half22float2(*reinterpret_cast<__half2*>(&h9[i].x));
        float2 f23 = __half22float2(*reinterpret_cast<__half2*>(&h9[i].y));
        acc4.x = fmaf(ws, f01.x, acc4.x);
        acc4.y = fmaf(ws, f01.y, acc4.y);
        acc4.z = fmaf(ws, f23.x, acc4.z);
        acc4.w = fmaf(ws, f23.y, acc4.w);
    }

    // ---- cross-group reduce (PART in dead W region; wsum-1 touched no smem
    //      besides wAr, so the write below only needs the final barrier) ----
    ((float4*)(smem + W_OFF))[wid * 32 + lane] = acc4;
    __syncthreads();

    if (tid < 32) {
        const float4* p = (const float4*)(smem + W_OFF);
        float4 s0 = p[tid];
#pragma unroll
        for (int k = 1; k < 8; k++) {
            float4 vv = p[k * 32 + tid];
            s0.x += vv.x; s0.y += vv.y; s0.z += vv.z; s0.w += vv.w;
        }
        *reinterpret_cast<float4*>(out + (size_t)b * ED + tid * 4) = s0;
    }
}

extern "C" void kernel_launch(void* const* d_in, const int* in_sizes, int n_in,
                              void* d_out, int out_size)
{
    const float* behav  = (const float*)d_in[0];
    const float* target = (const float*)d_in[1];
    const float* W1     = (const float*)d_in[2];
    const float* b1     = (const float*)d_in[3];
    const float* W2     = (const float*)d_in[4];
    const float* b2     = (const float*)d_in[5];
    float* out = (float*)d_out;

    const int B = in_sizes[1] / ED;   // 2048

    static bool attr_set = false;
    if (!attr_set) {
        cudaFuncSetAttribute(attn_din_kernel,
                             cudaFuncAttributeMaxDynamicSharedMemorySize, (int)SMEM_BYTES);
        attr_set = true;
    }

    attn_din_kernel<<<B, THREADS, SMEM_BYTES>>>(behav, target, W1, b1, W2, b2, out);
}

// round 17
// speedup vs baseline: 1.2235x; 1.0320x over previous
#include <cuda_runtime.h>
#include <cuda_fp16.h>
#include <cstdint>

#define ED   128
#define AD   64
#define THREADS 256
#define ROWB 272u        // padded row stride (136 fp16); frag loads conflict-free

// ---- shared memory layout (bytes) ----
#define A_OFF     0u         // 128 rows x 272 B = 34816
#define W_OFF     34816u     // 64 rows x 272 B = 17408 -> 52224 ; reused as float4 PART at the end
#define W2_OFF    52224u     // 64 f32 -> 52480
#define WARR_OFF  52480u     // 128 f32 -> 52992
#define CPART_OFF 52992u     // 128 f32 -> 53504
#define B2_OFF    53504u
#define SMEM_BYTES 53520u    // x3 CTAs = 160.6 KB (occ-3 with margin)

static __device__ __forceinline__ void mma16816(
    float c[4], const uint32_t a[4], uint32_t b0, uint32_t b1)
{
    asm volatile(
        "mma.sync.aligned.m16n8k16.row.col.f32.f16.f16.f32 "
        "{%0,%1,%2,%3}, {%4,%5,%6,%7}, {%8,%9}, {%0,%1,%2,%3};"
        : "+f"(c[0]), "+f"(c[1]), "+f"(c[2]), "+f"(c[3])
        : "r"(a[0]), "r"(a[1]), "r"(a[2]), "r"(a[3]), "r"(b0), "r"(b1));
}

__global__ void __launch_bounds__(THREADS, 3)
attn_din_kernel(const float* __restrict__ behav,
                const float* __restrict__ target,
                const float* __restrict__ W1,
                const float* __restrict__ b1,
                const float* __restrict__ W2,
                const float* __restrict__ b2,
                float* __restrict__ out)
{
    extern __shared__ char smem[];
    const int tid  = threadIdx.x;
    const int wid  = tid >> 5;
    const int lane = tid & 31;
    const int b    = blockIdx.x;

    float* w2S = (float*)(smem + W2_OFF);
    float* wAr = (float*)(smem + WARR_OFF);
    float* cP  = (float*)(smem + CPART_OFF);

    if (tid < AD) w2S[tid] = W2[tid];
    if (tid == 64) *((float*)(smem + B2_OFF)) = b2[0];

    const float4* bp = (const float4*)(behav + (size_t)b * 200 * ED);

    // ================= phase 0 (warp-specialized, balanced) =================
    if (wid < 4) {
        // warps 0-3: stage A rows 0..127 (fp16), warp w -> rows w, w+4, ... (MLP 16)
#pragma unroll 16
        for (int i = 0; i < 32; i++) {
            int r = wid + i * 4;
            float4 v = bp[r * 32 + lane];
            __half2 h01 = __floats2half2_rn(v.x, v.y);
            __half2 h23 = __floats2half2_rn(v.z, v.w);
            uint32_t off = (uint32_t)r * ROWB + (uint32_t)lane * 8u;
            *reinterpret_cast<uint2*>(smem + A_OFF + off) =
                make_uint2(*(uint32_t*)&h01, *(uint32_t*)&h23);
        }
    } else {
        // warps 4-7: build W_b[a][k] = Wx + Wd + t[k]*Wm (fp16) and c-partials.
        const int j  = tid - 128;
        const int a  = j & 63;
        const int kh = j >> 6;
        const float* tg  = target + (size_t)b * ED + kh * 64;
        const float* w1p = W1 + (size_t)(kh * 64) * AD + a;
        float cacc = (kh == 0) ? b1[a] : 0.f;
#pragma unroll 8
        for (int kk = 0; kk < 64; kk++) {
            float tk = tg[kk];                              // warp-broadcast, L2-hot
            float wx = w1p[kk * AD];                        // coalesced
            float wt = w1p[(128 * AD) + kk * AD];
            float wm = w1p[(256 * AD) + kk * AD];
            float wd = w1p[(384 * AD) + kk * AD];
            float w  = wx + wd + tk * wm;
            int k = kh * 64 + kk;
            *reinterpret_cast<__half*>(smem + W_OFF + (uint32_t)a * ROWB + (uint32_t)k * 2u)
                = __float2half_rn(w);
            cacc = fmaf(tk, wt - wd, cacc);
        }
        cP[j] = cacc;                                       // c[a] = cP[a] + cP[64+a]
    }
    __syncthreads();   // A[0..127], W, cP, w2S, b2 ready

    const int g  = lane >> 2;
    const int t2 = (lane & 3) * 2;
    const float b2v = *((const float*)(smem + B2_OFF));

    float4 acc4 = make_float4(0.f, 0.f, 0.f, 0.f);          // persistent weighted sums

    // ======================= half 0: GEMM + epilogue ========================
    {
        float acc[8][4];
#pragma unroll
        for (int n = 0; n < 8; n++)
#pragma unroll
            for (int i = 0; i < 4; i++) acc[n][i] = 0.f;

#pragma unroll
        for (int ks = 0; ks < 8; ks++) {
            const uint32_t kb = (uint32_t)(ks * 16 + t2) * 2u;
            const char* base = smem + A_OFF + (uint32_t)(wid * 16 + g) * ROWB + kb;
            uint32_t a[4];
            a[0] = *(const uint32_t*)(base);
            a[1] = *(const uint32_t*)(base + 8 * ROWB);
            a[2] = *(const uint32_t*)(base + 16);
            a[3] = *(const uint32_t*)(base + 8 * ROWB + 16);
#pragma unroll
            for (int n = 0; n < 8; n++) {
                const char* wb = smem + W_OFF + (uint32_t)(n * 8 + g) * ROWB + kb;
                uint32_t b0  = *(const uint32_t*)(wb);
                uint32_t b1r = *(const uint32_t*)(wb + 16);
                mma16816(acc[n], a, b0, b1r);
            }
        }

        float z[2] = {0.f, 0.f};
#pragma unroll
        for (int n = 0; n < 8; n++) {
            int col = n * 8 + t2;
            float c0 = cP[col]     + cP[64 + col];
            float c1 = cP[col + 1] + cP[65 + col];
#pragma unroll
            for (int h = 0; h < 2; h++) {
                float h0 = fmaxf(acc[n][2 * h]     + c0, 0.f);
                float h1 = fmaxf(acc[n][2 * h + 1] + c1, 0.f);
                z[h] = fmaf(h0, w2S[col], z[h]);
                z[h] = fmaf(h1, w2S[col + 1], z[h]);
            }
        }
#pragma unroll
        for (int h = 0; h < 2; h++) {
            float zz = z[h];
            zz += __shfl_xor_sync(0xFFFFFFFFu, zz, 1);
            zz += __shfl_xor_sync(0xFFFFFFFFu, zz, 2);
            if ((lane & 3) == 0)
                wAr[wid * 16 + h * 8 + g] = 1.f / (1.f + __expf(-(zz + b2v)));
        }
    }
    __syncthreads();   // wAr[0..127] ready

    // ===== prefetch half-1 rows into REGISTERS (loads overlap wsum-0) =====
    float4 v9[9];
#pragma unroll
    for (int i = 0; i < 9; i++)
        v9[i] = bp[(128 + wid * 9 + i) * 32 + lane];

    // ---- weighted sum half 0: thread (wid, lane) -> 4 e-values x 16 rows ----
    {
        const char* base = smem + A_OFF + (uint32_t)lane * 8u;
#pragma unroll 8
        for (int i = 0; i < 16; i++) {
            int s = wid * 16 + i;
            uint2 d = *reinterpret_cast<const uint2*>(base + (uint32_t)s * ROWB);
            float2 f01 = __half22float2(*reinterpret_cast<__half2*>(&d.x));
            float2 f23 = __half22float2(*reinterpret_cast<__half2*>(&d.y));
            float ws = wAr[s];
            acc4.x = fmaf(ws, f01.x, acc4.x);
            acc4.y = fmaf(ws, f01.y, acc4.y);
            acc4.z = fmaf(ws, f23.x, acc4.z);
            acc4.w = fmaf(ws, f23.y, acc4.w);
        }
    }
    __syncthreads();   // wsum-0 done reading A; v9 loads have had wsum-0 to land

    // ---- convert + store half-1 (72 rows); KEEP fp16 copies in registers ----
    uint2 h9[9];
#pragma unroll
    for (int i = 0; i < 9; i++) {
        int r = wid * 9 + i;           // local row 0..71
        __half2 h01 = __floats2half2_rn(v9[i].x, v9[i].y);
        __half2 h23 = __floats2half2_rn(v9[i].z, v9[i].w);
        h9[i] = make_uint2(*(uint32_t*)&h01, *(uint32_t*)&h23);
        uint32_t off = (uint32_t)r * ROWB + (uint32_t)lane * 8u;
        *reinterpret_cast<uint2*>(smem + A_OFF + off) = h9[i];
    }
    __syncthreads();   // A[0..71] = rows 128..199 ready

    // ======================= half 1: GEMM + epilogue ========================
    if (wid * 16 < 72) {               // warps 0-4
        float acc[8][4];
#pragma unroll
        for (int n = 0; n < 8; n++)
#pragma unroll
            for (int i = 0; i < 4; i++) acc[n][i] = 0.f;

#pragma unroll
        for (int ks = 0; ks < 8; ks++) {
            const uint32_t kb = (uint32_t)(ks * 16 + t2) * 2u;
            const char* base = smem + A_OFF + (uint32_t)(wid * 16 + g) * ROWB + kb;
            uint32_t a[4];
            a[0] = *(const uint32_t*)(base);
            a[1] = *(const uint32_t*)(base + 8 * ROWB);
            a[2] = *(const uint32_t*)(base + 16);
            a[3] = *(const uint32_t*)(base + 8 * ROWB + 16);
#pragma unroll
            for (int n = 0; n < 8; n++) {
                const char* wb = smem + W_OFF + (uint32_t)(n * 8 + g) * ROWB + kb;
                uint32_t b0  = *(const uint32_t*)(wb);
                uint32_t b1r = *(const uint32_t*)(wb + 16);
                mma16816(acc[n], a, b0, b1r);
            }
        }

        float z[2] = {0.f, 0.f};
#pragma unroll
        for (int n = 0; n < 8; n++) {
            int col = n * 8 + t2;
            float c0 = cP[col]     + cP[64 + col];
            float c1 = cP[col + 1] + cP[65 + col];
#pragma unroll
            for (int h = 0; h < 2; h++) {
                float h0 = fmaxf(acc[n][2 * h]     + c0, 0.f);
                float h1 = fmaxf(acc[n][2 * h + 1] + c1, 0.f);
                z[h] = fmaf(h0, w2S[col], z[h]);
                z[h] = fmaf(h1, w2S[col + 1], z[h]);
            }
        }
#pragma unroll
        for (int h = 0; h < 2; h++) {
            float zz = z[h];
            zz += __shfl_xor_sync(0xFFFFFFFFu, zz, 1);
            zz += __shfl_xor_sync(0xFFFFFFFFu, zz, 2);
            int s = wid * 16 + h * 8 + g;
            if ((lane & 3) == 0)
                wAr[s] = (s < 72) ? (1.f / (1.f + __expf(-(zz + b2v)))) : 0.f;
        }
    }
    __syncthreads();   // wAr[0..71] (half-1) ready

    // ---- weighted sum half 1: ENTIRELY from registers (h9) ----
#pragma unroll
    for (int i = 0; i < 9; i++) {
        float ws = wAr[wid * 9 + i];   // lane-uniform broadcast
        float2 f01 = __half22float2(*reinterpret_cast<__half2*>(&h9[i].x));
        float2 f23 = __half22float2(*reinterpret_cast<__half2*>(&h9[i].y));
        acc4.x = fmaf(ws, f01.x, acc4.x);
        acc4.y = fmaf(ws, f01.y, acc4.y);
        acc4.z = fmaf(ws, f23.x, acc4.z);
        acc4.w = fmaf(ws, f23.y, acc4.w);
    }

    // ---- cross-group reduce (PART in dead W region) and store ----
    ((float4*)(smem + W_OFF))[wid * 32 + lane] = acc4;
    __syncthreads();

    if (tid < 32) {
        const float4* p = (const float4*)(smem + W_OFF);
        float4 s0 = p[tid];
#pragma unroll
        for (int k = 1; k < 8; k++) {
            float4 vv = p[k * 32 + tid];
            s0.x += vv.x; s0.y += vv.y; s0.z += vv.z; s0.w += vv.w;
        }
        *reinterpret_cast<float4*>(out + (size_t)b * ED + tid * 4) = s0;
    }
}

extern "C" void kernel_launch(void* const* d_in, const int* in_sizes, int n_in,
                              void* d_out, int out_size)
{
    const float* behav  = (const float*)d_in[0];
    const float* target = (const float*)d_in[1];
    const float* W1     = (const float*)d_in[2];
    const float* b1     = (const float*)d_in[3];
    const float* W2     = (const float*)d_in[4];
    const float* b2     = (const float*)d_in[5];
    float* out = (float*)d_out;

    const int B = in_sizes[1] / ED;   // 2048

    static bool attr_set = false;
    if (!attr_set) {
        cudaFuncSetAttribute(attn_din_kernel,
                             cudaFuncAttributeMaxDynamicSharedMemorySize, (int)SMEM_BYTES);
        attr_set = true;
    }

    attn_din_kernel<<<B, THREADS, SMEM_BYTES>>>(behav, target, W1, b1, W2, b2, out);
}